// round 7
// baseline (speedup 1.0000x reference)
#include <cuda_runtime.h>
#include <cstdint>

#define N_NODES   50000
#define N_EDGES   800000
#define N_FEAT    128
#define N_CLASSES 64

// -------- device scratch (no cudaMalloc allowed) --------
__device__ int   g_is64;                                  // 1 if edge_index is int64
__device__ int   g_src[N_EDGES];
__device__ int   g_dst[N_EDGES];
__device__ int   g_cnt[N_NODES];                          // in-degree (excl. self loop)
__device__ int   g_fill[N_NODES];                         // CSR fill cursor
__device__ int   g_rowstart[N_NODES];                     // CSR row offsets
__device__ float g_dinv[N_NODES];                         // deg^-1/2
__device__ int   g_col[N_EDGES];                          // CSR column (src node)
__device__ __align__(16) float g_y [(size_t)N_NODES * N_CLASSES];  // x @ W^T
__device__ __align__(16) float g_h1[(size_t)N_NODES * N_CLASSES];
__device__ __align__(16) float g_h2[(size_t)N_NODES * N_CLASSES];

// ---------------------------------------------------------------------------
// dtype detection: int64 little-endian node ids (< 2^31) have all-zero odd
// 32-bit words in the first `words` words; int32 ids do not.
// ---------------------------------------------------------------------------
__global__ void k_flag_init() { g_is64 = 1; }

__global__ void k_detect(const int* __restrict__ buf, int words) {
    int i = blockIdx.x * blockDim.x + threadIdx.x;
    int idx = 2 * i + 1;
    if (idx < words && buf[idx] != 0) g_is64 = 0;   // benign race: all writers store 0
}

// Unpack src/dst as int32 regardless of storage dtype; clamp defensively.
__global__ void k_extract(const int* __restrict__ buf, int E, int N) {
    int e = blockIdx.x * blockDim.x + threadIdx.x;
    if (e >= E) return;
    int s, d;
    if (g_is64) {                       // int64 storage: low words at even offsets
        s = buf[2 * e];
        d = buf[2 * E + 2 * e];
    } else {                            // int32 storage
        s = buf[e];
        d = buf[E + e];
    }
    if ((unsigned)s >= (unsigned)N) s = 0;   // no-op on valid data; prevents traps
    if ((unsigned)d >= (unsigned)N) d = 0;
    g_src[e] = s;
    g_dst[e] = d;
}

// ---------------------------------------------------------------------------
// CSR build
// ---------------------------------------------------------------------------
__global__ void k_zero(int n) {
    int i = blockIdx.x * blockDim.x + threadIdx.x;
    if (i < n) { g_cnt[i] = 0; g_fill[i] = 0; }
}

__global__ void k_count(int E) {
    int e = blockIdx.x * blockDim.x + threadIdx.x;
    if (e < E) atomicAdd(&g_cnt[g_dst[e]], 1);
}

// single-block exclusive scan of g_cnt -> g_rowstart
__global__ void k_scan(int n) {
    __shared__ int partials[1024];
    const int tid  = threadIdx.x;
    const int CH   = (n + 1023) / 1024;
    const int base = tid * CH;

    int sum = 0;
    for (int k = 0; k < CH; k++) {
        int idx = base + k;
        if (idx < n) sum += g_cnt[idx];
    }
    partials[tid] = sum;
    __syncthreads();

    for (int off = 1; off < 1024; off <<= 1) {
        int v   = partials[tid];
        int add = (tid >= off) ? partials[tid - off] : 0;
        __syncthreads();
        partials[tid] = v + add;
        __syncthreads();
    }
    int run = (tid == 0) ? 0 : partials[tid - 1];

    for (int k = 0; k < CH; k++) {
        int idx = base + k;
        if (idx < n) { g_rowstart[idx] = run; run += g_cnt[idx]; }
    }
}

__global__ void k_fill(int E) {
    int e = blockIdx.x * blockDim.x + threadIdx.x;
    if (e >= E) return;
    int d = g_dst[e];
    int pos = g_rowstart[d] + atomicAdd(&g_fill[d], 1);
    g_col[pos] = g_src[e];
}

__global__ void k_dinv(int n) {
    int i = blockIdx.x * blockDim.x + threadIdx.x;
    if (i < n) g_dinv[i] = rsqrtf((float)(g_cnt[i] + 1));
}

// ---------------------------------------------------------------------------
// y = x @ W^T  (block per node, 64 threads; W = 32 KB stays L1-hot)
// ---------------------------------------------------------------------------
__global__ void k_lin(const float* __restrict__ x, const float* __restrict__ W, int n) {
    int i = blockIdx.x;
    if (i >= n) return;
    int c = threadIdx.x;                 // class 0..63
    __shared__ float xs[N_FEAT];

    const float* xr = x + (size_t)i * N_FEAT;
    xs[c]      = xr[c];
    xs[c + 64] = xr[c + 64];
    __syncthreads();

    const float* w = W + (size_t)c * N_FEAT;
    float acc = 0.0f;
    #pragma unroll
    for (int k = 0; k < N_FEAT; k += 4) {
        float4 wv = reinterpret_cast<const float4*>(w)[k >> 2];
        acc = fmaf(xs[k],     wv.x, acc);
        acc = fmaf(xs[k + 1], wv.y, acc);
        acc = fmaf(xs[k + 2], wv.z, acc);
        acc = fmaf(xs[k + 3], wv.w, acc);
    }
    g_y[(size_t)i * N_CLASSES + c] = acc;
}

// ---------------------------------------------------------------------------
// Propagation hop via CSR gather: no float atomics, deterministic.
// One warp per node; each lane owns one float2 (32 * 2 = 64 feats).
// ---------------------------------------------------------------------------
__device__ __forceinline__ void hop_body(const float* __restrict__ yin,
                                         float* __restrict__ yout) {
    int warp = (blockIdx.x * blockDim.x + threadIdx.x) >> 5;
    int lane = threadIdx.x & 31;
    if (warp >= N_NODES) return;
    const int   i  = warp;
    const float di = g_dinv[i];
    const int   rs = g_rowstart[i];
    const int   re = rs + g_cnt[i];

    float ax = 0.0f, ay = 0.0f;
    int e = rs;
    for (; e + 4 <= re; e += 4) {        // unroll x4: 4 outstanding gather chains
        int j0 = g_col[e],     j1 = g_col[e + 1];
        int j2 = g_col[e + 2], j3 = g_col[e + 3];
        float w0 = g_dinv[j0], w1 = g_dinv[j1];
        float w2 = g_dinv[j2], w3 = g_dinv[j3];
        float2 v0 = reinterpret_cast<const float2*>(yin + (size_t)j0 * N_CLASSES)[lane];
        float2 v1 = reinterpret_cast<const float2*>(yin + (size_t)j1 * N_CLASSES)[lane];
        float2 v2 = reinterpret_cast<const float2*>(yin + (size_t)j2 * N_CLASSES)[lane];
        float2 v3 = reinterpret_cast<const float2*>(yin + (size_t)j3 * N_CLASSES)[lane];
        ax = fmaf(w0, v0.x, ax); ay = fmaf(w0, v0.y, ay);
        ax = fmaf(w1, v1.x, ax); ay = fmaf(w1, v1.y, ay);
        ax = fmaf(w2, v2.x, ax); ay = fmaf(w2, v2.y, ay);
        ax = fmaf(w3, v3.x, ax); ay = fmaf(w3, v3.y, ay);
    }
    for (; e < re; e++) {
        int j = g_col[e];
        float w = g_dinv[j];
        float2 v = reinterpret_cast<const float2*>(yin + (size_t)j * N_CLASSES)[lane];
        ax = fmaf(w, v.x, ax); ay = fmaf(w, v.y, ay);
    }

    float2 self = reinterpret_cast<const float2*>(yin + (size_t)i * N_CLASSES)[lane];
    float2 o;
    o.x = fmaf(di, ax, di * di * self.x);
    o.y = fmaf(di, ay, di * di * self.y);
    reinterpret_cast<float2*>(yout + (size_t)i * N_CLASSES)[lane] = o;
}

__global__ void k_hop1() { hop_body(g_y,  g_h1); }
__global__ void k_hop2() { hop_body(g_h1, g_h2); }

// ---------------------------------------------------------------------------
// head: out = log_softmax(h2 + b)   (block per node, 64 threads)
// ---------------------------------------------------------------------------
__global__ void k_head(const float* __restrict__ b, float* __restrict__ out, int n) {
    int i = blockIdx.x;
    if (i >= n) return;
    int c = threadIdx.x;
    __shared__ float red_m[2];
    __shared__ float red_s[2];

    float acc = g_h2[(size_t)i * N_CLASSES + c] + b[c];

    float m = acc;
    #pragma unroll
    for (int o = 16; o; o >>= 1) m = fmaxf(m, __shfl_xor_sync(0xffffffffu, m, o));
    if ((c & 31) == 0) red_m[c >> 5] = m;
    __syncthreads();
    m = fmaxf(red_m[0], red_m[1]);

    float ex = __expf(acc - m);
    float ssum = ex;
    #pragma unroll
    for (int o = 16; o; o >>= 1) ssum += __shfl_xor_sync(0xffffffffu, ssum, o);
    if ((c & 31) == 0) red_s[c >> 5] = ssum;
    __syncthreads();
    float total = red_s[0] + red_s[1];

    out[(size_t)i * N_CLASSES + c] = acc - m - __logf(total);
}

// ---------------------------------------------------------------------------
// launch
// ---------------------------------------------------------------------------
extern "C" void kernel_launch(void* const* d_in, const int* in_sizes, int n_in,
                              void* d_out, int out_size) {
    // Robust input remap by element count (metadata order defense).
    int ix = 0, ie = 1, iw = 2, ib = 3;
    for (int k = 0; k < n_in && k < 4; k++) {
        if      (in_sizes[k] == N_NODES * N_FEAT)   ix = k;
        else if (in_sizes[k] == 2 * N_EDGES)        ie = k;
        else if (in_sizes[k] == N_CLASSES * N_FEAT) iw = k;
        else if (in_sizes[k] == N_CLASSES)          ib = k;
    }
    const float* x    = (const float*)d_in[ix];   // [N, 128]
    const int*   ebuf = (const int*)d_in[ie];     // [2, E] int32 or int64
    const float* W    = (const float*)d_in[iw];   // [64, 128]
    const float* b    = (const float*)d_in[ib];   // [64]
    float* out = (float*)d_out;

    const int N = N_NODES;
    const int E = N_EDGES;
    const int ewords = in_sizes[ie];              // safe word count for either dtype

    // dtype detect + unpack
    k_flag_init<<<1, 1>>>();
    k_detect <<<(ewords / 2 + 255) / 256, 256>>>(ebuf, ewords);
    k_extract<<<(E + 255) / 256, 256>>>(ebuf, E, N);

    // CSR build + norm
    k_zero <<<(N + 255) / 256, 256>>>(N);
    k_count<<<(E + 255) / 256, 256>>>(E);
    k_scan <<<1, 1024>>>(N);
    k_fill <<<(E + 255) / 256, 256>>>(E);
    k_dinv <<<(N + 255) / 256, 256>>>(N);

    // project first: y = x W^T  (propagation commutes with the linear map)
    k_lin<<<N, N_CLASSES>>>(x, W, N);

    // two hops, CSR gather
    const long long hop_threads = (long long)N * 32;
    const int hop_blocks = (int)((hop_threads + 255) / 256);
    k_hop1<<<hop_blocks, 256>>>();
    k_hop2<<<hop_blocks, 256>>>();

    // bias + log_softmax
    k_head<<<N, N_CLASSES>>>(b, out, N);
}